// round 13
// baseline (speedup 1.0000x reference)
#include <cuda_runtime.h>
#include <cuda_bf16.h>
#include <stdint.h>

#define NN 50000
#define EE 800000
#define DH 128
#define NH 8
#define SCAN_CHUNK 2048
#define NB ((NN + SCAN_CHUNK - 1) / SCAN_CHUNK)   // 25 scan blocks

// gemm dynamic smem: W resident (8 chunks x 128 cols x 24 u32) + x double buffer
#define WS_U32 (8 * 128 * 24)          // 24576 u32 = 96KB
#define XS_U32 (2 * 64 * 24)           // 3072 u32  = 12KB
#define GEMM_SMEM_BYTES ((WS_U32 + XS_U32) * 4)   // 110592

// ---------------- device scratch (no cudaMalloc allowed) ----------------
__device__ float    g_h[NN * DH];     // per-layer projected features h = x@W
__device__ float    g_o[NN * DH];     // layer-1 output (activated)
__device__ float    g_el[NN * NH];    // attention left logits
__device__ float    g_er[NN * NH];    // attention right logits
__device__ int      g_off[NN + 1];    // CSR row offsets (by dst)
__device__ int      g_cur[NN];        // scatter cursors
__device__ int      g_cnt[NN];        // in-degree histogram
__device__ int      g_csr[EE];        // src node per CSR slot
__device__ int      g_bsum[NB];
__device__ int      g_bbase[NB + 1];
// W split to bf16 hi/lo, fragment-layout chunk-major (see w_split_kernel)
__device__ uint32_t g_wt[128 * 128];  // 16384 u32 = 64KB

// ---------------- bf16 helpers ----------------
__device__ __forceinline__ uint32_t pack_bf16(float a, float b) {
    __nv_bfloat162 t = __floats2bfloat162_rn(a, b);
    return *(uint32_t*)&t;
}
__device__ __forceinline__ float bf16_hi(float v) {
    return __bfloat162float(__float2bfloat16_rn(v));
}
// D += A(16x16) * B(16x8), bf16 inputs, f32 accum
__device__ __forceinline__ void mma_bf16(float* c, const uint32_t* a,
                                         uint32_t b0, uint32_t b1) {
    asm("mma.sync.aligned.m16n8k16.row.col.f32.bf16.bf16.f32 "
        "{%0,%1,%2,%3}, {%4,%5,%6,%7}, {%8,%9}, {%0,%1,%2,%3};"
        : "+f"(c[0]), "+f"(c[1]), "+f"(c[2]), "+f"(c[3])
        : "r"(a[0]), "r"(a[1]), "r"(a[2]), "r"(a[3]), "r"(b0), "r"(b1));
}

// ---------------- W pre-split: fp32 -> bf16 hi/lo pairs, chunk-major ----------------
__global__ void w_split_kernel(const float* __restrict__ W, uint32_t* __restrict__ wt) {
    int i = blockIdx.x * 256 + threadIdx.x;   // 8192 pairs
    int c = (i >> 3) & 127;
    int kc = i >> 10;
    int p = i & 7;
    int k0 = kc * 16 + 2 * p;
    float v0 = W[k0 * 128 + c];
    float v1 = W[(k0 + 1) * 128 + c];
    float h0 = bf16_hi(v0), h1 = bf16_hi(v1);
    wt[i * 2]     = pack_bf16(h0, h1);
    wt[i * 2 + 1] = pack_bf16(v0 - h0, v1 - h1);
}

// ---------------- CSR build ----------------
__global__ void hist_kernel(const int* __restrict__ dst, int E) {
    int i = blockIdx.x * blockDim.x + threadIdx.x;
    if (i < E) atomicAdd(&g_cnt[dst[i]], 1);
}

__global__ __launch_bounds__(256) void partial_scan_kernel() {
    __shared__ int ws[8];
    int tid = threadIdx.x, lane = tid & 31, warp = tid >> 5;
    int base = blockIdx.x * SCAN_CHUNK + tid * 8;
    int v[8], s = 0;
    #pragma unroll
    for (int t = 0; t < 8; t++) {
        int i = base + t;
        v[t] = (i < NN) ? g_cnt[i] : 0;
        s += v[t];
    }
    int x = s;
    #pragma unroll
    for (int o = 1; o < 32; o <<= 1) {
        int y = __shfl_up_sync(0xffffffffu, x, o);
        if (lane >= o) x += y;
    }
    if (lane == 31) ws[warp] = x;
    __syncthreads();
    if (tid == 0) {
        int a = 0;
        #pragma unroll
        for (int w = 0; w < 8; w++) { int t = ws[w]; ws[w] = a; a += t; }
    }
    __syncthreads();
    int excl = ws[warp] + x - s;
    #pragma unroll
    for (int t = 0; t < 8; t++) {
        int i = base + t;
        if (i < NN) g_cnt[i] = excl;
        excl += v[t];
    }
    if (tid == 255) g_bsum[blockIdx.x] = ws[7] + x;
}

__global__ void scan_bsum_kernel() {
    int tid = threadIdx.x;
    int v = (tid < NB) ? g_bsum[tid] : 0;
    int x = v;
    #pragma unroll
    for (int o = 1; o < 32; o <<= 1) {
        int y = __shfl_up_sync(0xffffffffu, x, o);
        if (tid >= o) x += y;
    }
    if (tid < NB) g_bbase[tid] = x - v;
    if (tid == 31) g_bbase[NB] = x;
}

__global__ void finalize_kernel() {
    int i = blockIdx.x * blockDim.x + threadIdx.x;
    if (i < NN) {
        int off = g_cnt[i] + g_bbase[i / SCAN_CHUNK];
        g_off[i] = off;
        g_cur[i] = off;
        g_cnt[i] = 0;
    }
    if (i == 0) g_off[NN] = g_bbase[NB];
}

__global__ void scatter_kernel(const int* __restrict__ src,
                               const int* __restrict__ dst, int E) {
    int i = blockIdx.x * blockDim.x + threadIdx.x;
    if (i < E) {
        int p = atomicAdd(&g_cur[dst[i]], 1);
        g_csr[p] = src[i];
    }
}

// ---------------- GEMM via bf16 mma (3xBF16) + fused attn projections ----------------
// W resident in smem for the whole kernel (96KB, conflict-free stride-12-u64
// per chunk); x double-buffered (prefetch to regs during mma). Steady-state
// inner loop: x store + 16 LDS.64 + 24 mma, one sync. el/er fused in epilogue.
__global__ __launch_bounds__(256) void gemm_mma(
    const float* __restrict__ x, const uint32_t* __restrict__ wt,
    const float* __restrict__ al, const float* __restrict__ ar,
    float* __restrict__ h, float* __restrict__ el, float* __restrict__ er) {
    extern __shared__ uint32_t smem[];
    uint32_t* ws = smem;               // WS_U32
    uint32_t* xs = smem + WS_U32;      // XS_U32
    int tid = threadIdx.x, lane = tid & 31, warp = tid >> 5;
    int g = lane >> 2, t = lane & 3;
    int row0 = blockIdx.x * 64;
    int mh = (warp & 1) * 32;        // m-half
    int nq = (warp >> 1) * 32;       // n-quarter (2 heads)
    int xr = tid >> 2, xq = tid & 3; // x-fill coords

    float c[2][4][4];
    #pragma unroll
    for (int mi = 0; mi < 2; mi++)
        #pragma unroll
        for (int j = 0; j < 4; j++)
            #pragma unroll
            for (int q = 0; q < 4; q++) c[mi][j][q] = 0.f;

    // prologue: whole W -> smem (8 chunks x 512 uint4), x chunk 0 -> buffer 0
    #pragma unroll
    for (int e = 0; e < 16; e++) {
        int i = tid + e * 256;            // uint4 index into g_wt (4096 total)
        int kc = i >> 9;                  // 512 uint4 per chunk
        int r = i & 511;
        uint4 v = ((const uint4*)wt)[i];
        ((uint4*)(ws + kc * 3072))[(r >> 2) * 6 + (r & 3)] = v;
    }
    {
        float4 v = make_float4(0.f, 0.f, 0.f, 0.f);
        if (row0 + xr < NN) v = ((const float4*)x)[(row0 + xr) * 32 + xq];
        float hx = bf16_hi(v.x), hy = bf16_hi(v.y);
        float hz = bf16_hi(v.z), hw = bf16_hi(v.w);
        uint4 o;
        o.x = pack_bf16(hx, hy);
        o.y = pack_bf16(v.x - hx, v.y - hy);
        o.z = pack_bf16(hz, hw);
        o.w = pack_bf16(v.z - hz, v.w - hw);
        ((uint4*)xs)[xr * 6 + xq] = o;
    }

    for (int kc = 0; kc < 8; kc++) {
        __syncthreads();
        int cur = kc & 1, nxt = cur ^ 1;
        const uint2* xs2 = (const uint2*)(xs + cur * 1536);
        const uint2* ws2 = (const uint2*)(ws + kc * 3072);

        // prefetch next x chunk to registers
        float4 xv_n = make_float4(0.f, 0.f, 0.f, 0.f);
        if (kc < 7 && row0 + xr < NN)
            xv_n = ((const float4*)x)[(row0 + xr) * 32 + (kc + 1) * 4 + xq];

        // fragment loads + mma
        uint32_t ah[2][4], al_[2][4];
        #pragma unroll
        for (int mi = 0; mi < 2; mi++) {
            int mb = (mh + mi * 16 + g) * 12;
            uint2 v0 = xs2[mb + t];
            uint2 v1 = xs2[mb + 96 + t];
            uint2 v2 = xs2[mb + 4 + t];
            uint2 v3 = xs2[mb + 100 + t];
            ah[mi][0] = v0.x; al_[mi][0] = v0.y;
            ah[mi][1] = v1.x; al_[mi][1] = v1.y;
            ah[mi][2] = v2.x; al_[mi][2] = v2.y;
            ah[mi][3] = v3.x; al_[mi][3] = v3.y;
        }
        #pragma unroll
        for (int j = 0; j < 4; j++) {
            int cb = (nq + j * 8 + g) * 12;
            uint2 b0 = ws2[cb + t];
            uint2 b1 = ws2[cb + 4 + t];
            #pragma unroll
            for (int mi = 0; mi < 2; mi++) {
                mma_bf16(c[mi][j], ah[mi],  b0.x, b1.x);   // hi*hi
                mma_bf16(c[mi][j], al_[mi], b0.x, b1.x);   // lo*hi
                mma_bf16(c[mi][j], ah[mi],  b0.y, b1.y);   // hi*lo
            }
        }

        // store prefetched x chunk to the other buffer
        if (kc < 7) {
            float hx = bf16_hi(xv_n.x), hy = bf16_hi(xv_n.y);
            float hz = bf16_hi(xv_n.z), hw = bf16_hi(xv_n.w);
            uint4 o;
            o.x = pack_bf16(hx, hy);
            o.y = pack_bf16(xv_n.x - hx, xv_n.y - hy);
            o.z = pack_bf16(hz, hw);
            o.w = pack_bf16(xv_n.z - hz, xv_n.w - hw);
            ((uint4*)(xs + nxt * 1536))[xr * 6 + xq] = o;
        }
    }

    // epilogue: write h
    #pragma unroll
    for (int mi = 0; mi < 2; mi++)
        #pragma unroll
        for (int j = 0; j < 4; j++) {
            int col = nq + j * 8 + 2 * t;
            int r0 = row0 + mh + mi * 16 + g;
            if (r0 < NN)
                *(float2*)&h[r0 * DH + col] = make_float2(c[mi][j][0], c[mi][j][1]);
            if (r0 + 8 < NN)
                *(float2*)&h[(r0 + 8) * DH + col] = make_float2(c[mi][j][2], c[mi][j][3]);
        }

    // fused attn projections: el/er for this warp's 2 heads, 32 rows
    {
        const float2* alp = (const float2*)al;
        const float2* arp = (const float2*)ar;
        float2 a_l[4], a_r[4];
        #pragma unroll
        for (int j = 0; j < 4; j++) {
            a_l[j] = alp[(nq >> 1) + j * 4 + t];
            a_r[j] = arp[(nq >> 1) + j * 4 + t];
        }
        int head0 = nq >> 4;
        #pragma unroll
        for (int mi = 0; mi < 2; mi++) {
            float e[8];
            e[0] = c[mi][0][0]*a_l[0].x + c[mi][0][1]*a_l[0].y + c[mi][1][0]*a_l[1].x + c[mi][1][1]*a_l[1].y;
            e[1] = c[mi][2][0]*a_l[2].x + c[mi][2][1]*a_l[2].y + c[mi][3][0]*a_l[3].x + c[mi][3][1]*a_l[3].y;
            e[2] = c[mi][0][2]*a_l[0].x + c[mi][0][3]*a_l[0].y + c[mi][1][2]*a_l[1].x + c[mi][1][3]*a_l[1].y;
            e[3] = c[mi][2][2]*a_l[2].x + c[mi][2][3]*a_l[2].y + c[mi][3][2]*a_l[3].x + c[mi][3][3]*a_l[3].y;
            e[4] = c[mi][0][0]*a_r[0].x + c[mi][0][1]*a_r[0].y + c[mi][1][0]*a_r[1].x + c[mi][1][1]*a_r[1].y;
            e[5] = c[mi][2][0]*a_r[2].x + c[mi][2][1]*a_r[2].y + c[mi][3][0]*a_r[3].x + c[mi][3][1]*a_r[3].y;
            e[6] = c[mi][0][2]*a_r[0].x + c[mi][0][3]*a_r[0].y + c[mi][1][2]*a_r[1].x + c[mi][1][3]*a_r[1].y;
            e[7] = c[mi][2][2]*a_r[2].x + c[mi][2][3]*a_r[2].y + c[mi][3][2]*a_r[3].x + c[mi][3][3]*a_r[3].y;
            #pragma unroll
            for (int q = 0; q < 8; q++) {
                e[q] += __shfl_xor_sync(0xffffffffu, e[q], 1);
                e[q] += __shfl_xor_sync(0xffffffffu, e[q], 2);
            }
            if (t == 0) {
                int r0 = row0 + mh + mi * 16 + g;
                if (r0 < NN) {
                    el[r0 * NH + head0]     = e[0];
                    el[r0 * NH + head0 + 1] = e[1];
                    er[r0 * NH + head0]     = e[4];
                    er[r0 * NH + head0 + 1] = e[5];
                }
                if (r0 + 8 < NN) {
                    el[(r0 + 8) * NH + head0]     = e[2];
                    el[(r0 + 8) * NH + head0 + 1] = e[3];
                    er[(r0 + 8) * NH + head0]     = e[6];
                    er[(r0 + 8) * NH + head0 + 1] = e[7];
                }
            }
        }
    }
}

// ---------------- fused edge softmax + aggregation: one warp per dst node ----------------
__global__ __launch_bounds__(256) void agg_kernel(
    const float* __restrict__ h, const float* __restrict__ el,
    const float* __restrict__ er, float* __restrict__ out, int act) {
    int w = blockIdx.x * 8 + (threadIdx.x >> 5);
    if (w >= NN) return;
    int lane = threadIdx.x & 31;
    int head = lane >> 2;
    int beg = g_off[w], end = g_off[w + 1];

    float erh = __ldg(&er[w * NH + head]);

    float4 accA = make_float4(0.f, 0.f, 0.f, 0.f);
    float4 accB = make_float4(0.f, 0.f, 0.f, 0.f);
    float zA = 0.f, zB = 0.f;

    int j = beg;
    for (; j + 1 < end; j += 2) {
        int sA = g_csr[j];
        int sB = g_csr[j + 1];
        float vA = __ldg(&el[sA * NH + head]) + erh;
        float vB = __ldg(&el[sB * NH + head]) + erh;
        vA = vA > 0.f ? vA : 0.2f * vA;
        vB = vB > 0.f ? vB : 0.2f * vB;
        float aA = __expf(vA);
        float aB = __expf(vB);
        float4 hA = ((const float4*)h)[sA * 32 + lane];
        float4 hB = ((const float4*)h)[sB * 32 + lane];
        zA += aA;
        zB += aB;
        accA.x = fmaf(aA, hA.x, accA.x);
        accA.y = fmaf(aA, hA.y, accA.y);
        accA.z = fmaf(aA, hA.z, accA.z);
        accA.w = fmaf(aA, hA.w, accA.w);
        accB.x = fmaf(aB, hB.x, accB.x);
        accB.y = fmaf(aB, hB.y, accB.y);
        accB.z = fmaf(aB, hB.z, accB.z);
        accB.w = fmaf(aB, hB.w, accB.w);
    }
    if (j < end) {
        int s = g_csr[j];
        float v = __ldg(&el[s * NH + head]) + erh;
        v = v > 0.f ? v : 0.2f * v;
        float a = __expf(v);
        float4 hv = ((const float4*)h)[s * 32 + lane];
        zA += a;
        accA.x = fmaf(a, hv.x, accA.x);
        accA.y = fmaf(a, hv.y, accA.y);
        accA.z = fmaf(a, hv.z, accA.z);
        accA.w = fmaf(a, hv.w, accA.w);
    }

    float z = zA + zB;
    float4 acc = make_float4(accA.x + accB.x, accA.y + accB.y,
                             accA.z + accB.z, accA.w + accB.w);
    float invz = (end > beg) ? 1.0f / z : 0.f;   // deg-0 -> output 0 (matches ref)
    acc.x *= invz; acc.y *= invz; acc.z *= invz; acc.w *= invz;

    if (act) {
        acc.x = acc.x > 0.f ? acc.x : 0.01f * acc.x;
        acc.y = acc.y > 0.f ? acc.y : 0.01f * acc.y;
        acc.z = acc.z > 0.f ? acc.z : 0.01f * acc.z;
        acc.w = acc.w > 0.f ? acc.w : 0.01f * acc.w;
    }
    ((float4*)out)[w * 32 + lane] = acc;
}

// ---------------- launch ----------------
// Two-stream graph (CSR chain || layer-1 compute); gemm1 is my 4th launch
// so ncu -s 5 (two harness launches ahead) captures it.
extern "C" void kernel_launch(void* const* d_in, const int* in_sizes, int n_in,
                              void* d_out, int out_size) {
    const float* x   = (const float*)d_in[0];
    const int*   src = (const int*)d_in[1];
    const int*   dst = (const int*)d_in[2];
    const float* W1  = (const float*)d_in[3];
    const float* al1 = (const float*)d_in[4];
    const float* ar1 = (const float*)d_in[5];
    const float* W2  = (const float*)d_in[6];
    const float* al2 = (const float*)d_in[7];
    const float* ar2 = (const float*)d_in[8];
    float* out = (float*)d_out;
    int E = in_sizes[1];

    float *ph, *po, *pel, *per;
    uint32_t *pwt;
    cudaGetSymbolAddress((void**)&ph,  g_h);
    cudaGetSymbolAddress((void**)&po,  g_o);
    cudaGetSymbolAddress((void**)&pel, g_el);
    cudaGetSymbolAddress((void**)&per, g_er);
    cudaGetSymbolAddress((void**)&pwt, g_wt);

    // one-time host-side resources (no device memory involved)
    static cudaStream_t s2 = nullptr;
    static cudaEvent_t ev_fork = nullptr, ev_csr = nullptr,
                       ev_gemm1 = nullptr, ev_w2 = nullptr;
    if (s2 == nullptr) {
        cudaStreamCreateWithFlags(&s2, cudaStreamNonBlocking);
        cudaEventCreateWithFlags(&ev_fork,  cudaEventDisableTiming);
        cudaEventCreateWithFlags(&ev_csr,   cudaEventDisableTiming);
        cudaEventCreateWithFlags(&ev_gemm1, cudaEventDisableTiming);
        cudaEventCreateWithFlags(&ev_w2,    cudaEventDisableTiming);
        cudaFuncSetAttribute(gemm_mma,
                             cudaFuncAttributeMaxDynamicSharedMemorySize,
                             GEMM_SMEM_BYTES);
    }

    const int GB = (NN + 63) / 64;   // gemm blocks

    cudaEventRecord(ev_fork, 0);
    cudaStreamWaitEvent(s2, ev_fork, 0);

    w_split_kernel<<<32, 256>>>(W1, pwt);                                   // 0 main
    hist_kernel<<<(E + 255) / 256, 256, 0, s2>>>(dst, E);                   // 1 s2
    partial_scan_kernel<<<NB, 256, 0, s2>>>();                              // 2 s2
    gemm_mma<<<GB, 256, GEMM_SMEM_BYTES>>>(x, pwt, al1, ar1, ph, pel, per); // 3 main (ncu)
    scan_bsum_kernel<<<1, 32, 0, s2>>>();                                   // 4 s2
    finalize_kernel<<<(NN + 255) / 256, 256, 0, s2>>>();                    // 5 s2
    scatter_kernel<<<(E + 255) / 256, 256, 0, s2>>>(src, dst, E);           // 6 s2
    cudaEventRecord(ev_csr, s2);
    cudaEventRecord(ev_gemm1, 0);

    // wsplit2 on side stream after gemm1 releases g_wt
    cudaStreamWaitEvent(s2, ev_gemm1, 0);
    w_split_kernel<<<32, 256, 0, s2>>>(W2, pwt);                            // 7 s2
    cudaEventRecord(ev_w2, s2);

    // join: agg1 needs the CSR (and gemm1, same stream)
    cudaStreamWaitEvent(0, ev_csr, 0);
    agg_kernel<<<NN / 8, 256>>>(ph, pel, per, po, 1);                       // 8 main

    // layer 2
    cudaStreamWaitEvent(0, ev_w2, 0);
    gemm_mma<<<GB, 256, GEMM_SMEM_BYTES>>>(po, pwt, al2, ar2, ph, pel, per);// 9 main
    agg_kernel<<<NN / 8, 256>>>(ph, pel, per, out, 0);                      // 10 main
}

// round 14
// speedup vs baseline: 1.0332x; 1.0332x over previous
#include <cuda_runtime.h>
#include <cuda_bf16.h>
#include <stdint.h>

#define NN 50000
#define EE 800000
#define DH 128
#define NH 8
#define SCAN_CHUNK 2048
#define NB ((NN + SCAN_CHUNK - 1) / SCAN_CHUNK)   // 25 scan blocks

// ---------------- device scratch (no cudaMalloc allowed) ----------------
__device__ float    g_h[NN * DH];     // per-layer projected features h = x@W
__device__ float    g_el[NN * NH];    // attention left logits
__device__ float    g_er[NN * NH];    // attention right logits
__device__ int      g_off[NN + 1];    // CSR row offsets (by dst)
__device__ int      g_cur[NN];        // scatter cursors
__device__ int      g_cnt[NN];        // in-degree histogram
__device__ int      g_csr[EE];        // src node per CSR slot
__device__ int      g_bsum[NB];
__device__ int      g_bbase[NB + 1];
// W split to bf16 hi/lo, fragment-layout chunk-major (see w_split_kernel)
__device__ uint32_t g_wt[128 * 128];  // 64KB
// x split to bf16 hi/lo pairs, row-major: u32 idx row*128 + 4*pair_pair...
// pair p (k=2p,2p+1) of row r: hi at u32 r*128+2p, lo at r*128+2p+1.
__device__ uint32_t g_xs[NN * 128];   // 25.6MB

// ---------------- bf16 helpers ----------------
__device__ __forceinline__ uint32_t pack_bf16(float a, float b) {
    __nv_bfloat162 t = __floats2bfloat162_rn(a, b);
    return *(uint32_t*)&t;
}
__device__ __forceinline__ float bf16_hi(float v) {
    return __bfloat162float(__float2bfloat16_rn(v));
}
// split float4 (2 pairs) -> uint4 {hi01, lo01, hi23, lo23}
__device__ __forceinline__ uint4 split4(float4 v) {
    float hx = bf16_hi(v.x), hy = bf16_hi(v.y);
    float hz = bf16_hi(v.z), hw = bf16_hi(v.w);
    uint4 o;
    o.x = pack_bf16(hx, hy);
    o.y = pack_bf16(v.x - hx, v.y - hy);
    o.z = pack_bf16(hz, hw);
    o.w = pack_bf16(v.z - hz, v.w - hw);
    return o;
}
// D += A(16x16) * B(16x8), bf16 inputs, f32 accum
__device__ __forceinline__ void mma_bf16(float* c, const uint32_t* a,
                                         uint32_t b0, uint32_t b1) {
    asm("mma.sync.aligned.m16n8k16.row.col.f32.bf16.bf16.f32 "
        "{%0,%1,%2,%3}, {%4,%5,%6,%7}, {%8,%9}, {%0,%1,%2,%3};"
        : "+f"(c[0]), "+f"(c[1]), "+f"(c[2]), "+f"(c[3])
        : "r"(a[0]), "r"(a[1]), "r"(a[2]), "r"(a[3]), "r"(b0), "r"(b1));
}

// ---------------- pre-split kernels ----------------
__global__ void w_split_kernel(const float* __restrict__ W, uint32_t* __restrict__ wt) {
    int i = blockIdx.x * 256 + threadIdx.x;   // 8192 pairs
    int c = (i >> 3) & 127;
    int kc = i >> 10;
    int p = i & 7;
    int k0 = kc * 16 + 2 * p;
    float v0 = W[k0 * 128 + c];
    float v1 = W[(k0 + 1) * 128 + c];
    float h0 = bf16_hi(v0), h1 = bf16_hi(v1);
    wt[i * 2]     = pack_bf16(h0, h1);
    wt[i * 2 + 1] = pack_bf16(v0 - h0, v1 - h1);
}

// x fp32 -> bf16 hi/lo pair array (layer-1 input)
__global__ void x_split_kernel(const float* __restrict__ x, uint32_t* __restrict__ xs) {
    int i = blockIdx.x * 256 + threadIdx.x;   // over NN*32 uint4s
    if (i < NN * 32) {
        float4 v = ((const float4*)x)[i];
        ((uint4*)xs)[i] = split4(v);
    }
}

// ---------------- CSR build ----------------
__global__ void hist_kernel(const int* __restrict__ dst, int E) {
    int i = blockIdx.x * blockDim.x + threadIdx.x;
    if (i < E) atomicAdd(&g_cnt[dst[i]], 1);
}

__global__ __launch_bounds__(256) void partial_scan_kernel() {
    __shared__ int ws[8];
    int tid = threadIdx.x, lane = tid & 31, warp = tid >> 5;
    int base = blockIdx.x * SCAN_CHUNK + tid * 8;
    int v[8], s = 0;
    #pragma unroll
    for (int t = 0; t < 8; t++) {
        int i = base + t;
        v[t] = (i < NN) ? g_cnt[i] : 0;
        s += v[t];
    }
    int x = s;
    #pragma unroll
    for (int o = 1; o < 32; o <<= 1) {
        int y = __shfl_up_sync(0xffffffffu, x, o);
        if (lane >= o) x += y;
    }
    if (lane == 31) ws[warp] = x;
    __syncthreads();
    if (tid == 0) {
        int a = 0;
        #pragma unroll
        for (int w = 0; w < 8; w++) { int t = ws[w]; ws[w] = a; a += t; }
    }
    __syncthreads();
    int excl = ws[warp] + x - s;
    #pragma unroll
    for (int t = 0; t < 8; t++) {
        int i = base + t;
        if (i < NN) g_cnt[i] = excl;
        excl += v[t];
    }
    if (tid == 255) g_bsum[blockIdx.x] = ws[7] + x;
}

__global__ void scan_bsum_kernel() {
    int tid = threadIdx.x;
    int v = (tid < NB) ? g_bsum[tid] : 0;
    int x = v;
    #pragma unroll
    for (int o = 1; o < 32; o <<= 1) {
        int y = __shfl_up_sync(0xffffffffu, x, o);
        if (tid >= o) x += y;
    }
    if (tid < NB) g_bbase[tid] = x - v;
    if (tid == 31) g_bbase[NB] = x;
}

__global__ void finalize_kernel() {
    int i = blockIdx.x * blockDim.x + threadIdx.x;
    if (i < NN) {
        int off = g_cnt[i] + g_bbase[i / SCAN_CHUNK];
        g_off[i] = off;
        g_cur[i] = off;
        g_cnt[i] = 0;
    }
    if (i == 0) g_off[NN] = g_bbase[NB];
}

__global__ void scatter_kernel(const int* __restrict__ src,
                               const int* __restrict__ dst, int E) {
    int i = blockIdx.x * blockDim.x + threadIdx.x;
    if (i < E) {
        int p = atomicAdd(&g_cur[dst[i]], 1);
        g_csr[p] = src[i];
    }
}

// ---------------- GEMM via bf16 mma (3xBF16) + fused attn projections ----------------
// x pre-split (g_xs): chunk fills are pure uint4 copies -> no cvt/pack in loop.
// Per-chunk double-buffered smem (R12 structure). el/er fused in epilogue.
__global__ __launch_bounds__(256) void gemm_mma(
    const uint32_t* __restrict__ xsp, const uint32_t* __restrict__ wt,
    const float* __restrict__ al, const float* __restrict__ ar,
    float* __restrict__ h, float* __restrict__ el, float* __restrict__ er) {
    __shared__ uint32_t xs[2 * 64 * 24];    // 12KB
    __shared__ uint32_t ws[2 * 128 * 24];   // 24KB
    int tid = threadIdx.x, lane = tid & 31, warp = tid >> 5;
    int g = lane >> 2, t = lane & 3;
    int row0 = blockIdx.x * 64;
    int mh = (warp & 1) * 32;        // m-half
    int nq = (warp >> 1) * 32;       // n-quarter (2 heads)
    int xr = tid >> 2, xq = tid & 3; // x-fill coords

    float c[2][4][4];
    #pragma unroll
    for (int mi = 0; mi < 2; mi++)
        #pragma unroll
        for (int j = 0; j < 4; j++)
            #pragma unroll
            for (int q = 0; q < 4; q++) c[mi][j][q] = 0.f;

    // prologue: chunk 0 -> buffer 0 (pure copies)
    {
        uint4 o = make_uint4(0u, 0u, 0u, 0u);
        if (row0 + xr < NN) o = ((const uint4*)xsp)[(row0 + xr) * 32 + xq];
        ((uint4*)xs)[xr * 6 + xq] = o;
        #pragma unroll
        for (int e = 0; e < 2; e++) {
            int i = tid + e * 256;
            uint4 wv = ((const uint4*)wt)[i];
            ((uint4*)ws)[(i >> 2) * 6 + (i & 3)] = wv;
        }
    }

    for (int kc = 0; kc < 8; kc++) {
        __syncthreads();
        int cur = kc & 1, nxt = cur ^ 1;
        const uint2* xs2 = (const uint2*)xs + cur * 768;
        const uint2* ws2 = (const uint2*)ws + cur * 1536;

        // prefetch next chunk to registers (pure loads)
        uint4 xv_n = make_uint4(0u, 0u, 0u, 0u);
        uint4 wv0_n, wv1_n;
        if (kc < 7) {
            if (row0 + xr < NN)
                xv_n = ((const uint4*)xsp)[(row0 + xr) * 32 + (kc + 1) * 4 + xq];
            wv0_n = ((const uint4*)(wt + (kc + 1) * 2048))[tid];
            wv1_n = ((const uint4*)(wt + (kc + 1) * 2048))[tid + 256];
        }

        // fragment loads + mma on current buffer
        uint32_t ah[2][4], al_[2][4];
        #pragma unroll
        for (int mi = 0; mi < 2; mi++) {
            int mb = (mh + mi * 16 + g) * 12;
            uint2 v0 = xs2[mb + t];
            uint2 v1 = xs2[mb + 96 + t];
            uint2 v2 = xs2[mb + 4 + t];
            uint2 v3 = xs2[mb + 100 + t];
            ah[mi][0] = v0.x; al_[mi][0] = v0.y;
            ah[mi][1] = v1.x; al_[mi][1] = v1.y;
            ah[mi][2] = v2.x; al_[mi][2] = v2.y;
            ah[mi][3] = v3.x; al_[mi][3] = v3.y;
        }
        #pragma unroll
        for (int j = 0; j < 4; j++) {
            int cb = (nq + j * 8 + g) * 12;
            uint2 b0 = ws2[cb + t];
            uint2 b1 = ws2[cb + 4 + t];
            #pragma unroll
            for (int mi = 0; mi < 2; mi++) {
                mma_bf16(c[mi][j], ah[mi],  b0.x, b1.x);   // hi*hi
                mma_bf16(c[mi][j], al_[mi], b0.x, b1.x);   // lo*hi
                mma_bf16(c[mi][j], ah[mi],  b0.y, b1.y);   // hi*lo
            }
        }

        // store prefetched chunk to the other buffer (pure copies)
        if (kc < 7) {
            ((uint4*)xs)[nxt * 384 + xr * 6 + xq] = xv_n;
            ((uint4*)ws)[nxt * 768 + (tid >> 2) * 6 + (tid & 3)] = wv0_n;
            int i = tid + 256;
            ((uint4*)ws)[nxt * 768 + (i >> 2) * 6 + (i & 3)] = wv1_n;
        }
    }

    // epilogue: write h
    #pragma unroll
    for (int mi = 0; mi < 2; mi++)
        #pragma unroll
        for (int j = 0; j < 4; j++) {
            int col = nq + j * 8 + 2 * t;
            int r0 = row0 + mh + mi * 16 + g;
            if (r0 < NN)
                *(float2*)&h[r0 * DH + col] = make_float2(c[mi][j][0], c[mi][j][1]);
            if (r0 + 8 < NN)
                *(float2*)&h[(r0 + 8) * DH + col] = make_float2(c[mi][j][2], c[mi][j][3]);
        }

    // fused attn projections: el/er for this warp's 2 heads, 32 rows
    {
        const float2* alp = (const float2*)al;
        const float2* arp = (const float2*)ar;
        float2 a_l[4], a_r[4];
        #pragma unroll
        for (int j = 0; j < 4; j++) {
            a_l[j] = alp[(nq >> 1) + j * 4 + t];
            a_r[j] = arp[(nq >> 1) + j * 4 + t];
        }
        int head0 = nq >> 4;
        #pragma unroll
        for (int mi = 0; mi < 2; mi++) {
            float e[8];
            e[0] = c[mi][0][0]*a_l[0].x + c[mi][0][1]*a_l[0].y + c[mi][1][0]*a_l[1].x + c[mi][1][1]*a_l[1].y;
            e[1] = c[mi][2][0]*a_l[2].x + c[mi][2][1]*a_l[2].y + c[mi][3][0]*a_l[3].x + c[mi][3][1]*a_l[3].y;
            e[2] = c[mi][0][2]*a_l[0].x + c[mi][0][3]*a_l[0].y + c[mi][1][2]*a_l[1].x + c[mi][1][3]*a_l[1].y;
            e[3] = c[mi][2][2]*a_l[2].x + c[mi][2][3]*a_l[2].y + c[mi][3][2]*a_l[3].x + c[mi][3][3]*a_l[3].y;
            e[4] = c[mi][0][0]*a_r[0].x + c[mi][0][1]*a_r[0].y + c[mi][1][0]*a_r[1].x + c[mi][1][1]*a_r[1].y;
            e[5] = c[mi][2][0]*a_r[2].x + c[mi][2][1]*a_r[2].y + c[mi][3][0]*a_r[3].x + c[mi][3][1]*a_r[3].y;
            e[6] = c[mi][0][2]*a_r[0].x + c[mi][0][3]*a_r[0].y + c[mi][1][2]*a_r[1].x + c[mi][1][3]*a_r[1].y;
            e[7] = c[mi][2][2]*a_r[2].x + c[mi][2][3]*a_r[2].y + c[mi][3][2]*a_r[3].x + c[mi][3][3]*a_r[3].y;
            #pragma unroll
            for (int q = 0; q < 8; q++) {
                e[q] += __shfl_xor_sync(0xffffffffu, e[q], 1);
                e[q] += __shfl_xor_sync(0xffffffffu, e[q], 2);
            }
            if (t == 0) {
                int r0 = row0 + mh + mi * 16 + g;
                if (r0 < NN) {
                    el[r0 * NH + head0]     = e[0];
                    el[r0 * NH + head0 + 1] = e[1];
                    er[r0 * NH + head0]     = e[4];
                    er[r0 * NH + head0 + 1] = e[5];
                }
                if (r0 + 8 < NN) {
                    el[(r0 + 8) * NH + head0]     = e[2];
                    el[(r0 + 8) * NH + head0 + 1] = e[3];
                    er[(r0 + 8) * NH + head0]     = e[6];
                    er[(r0 + 8) * NH + head0 + 1] = e[7];
                }
            }
        }
    }
}

// ---------------- fused edge softmax + aggregation: one warp per dst node ----------------
// mode 1 (layer 1): apply leaky_relu(0.01) and write bf16 hi/lo split (feeds gemm2).
// mode 0 (layer 2): write fp32 to out (final output).
__global__ __launch_bounds__(256) void agg_kernel(
    const float* __restrict__ h, const float* __restrict__ el,
    const float* __restrict__ er, float* __restrict__ outf,
    uint32_t* __restrict__ outs, int mode) {
    int w = blockIdx.x * 8 + (threadIdx.x >> 5);
    if (w >= NN) return;
    int lane = threadIdx.x & 31;
    int head = lane >> 2;
    int beg = g_off[w], end = g_off[w + 1];

    float erh = __ldg(&er[w * NH + head]);

    float4 accA = make_float4(0.f, 0.f, 0.f, 0.f);
    float4 accB = make_float4(0.f, 0.f, 0.f, 0.f);
    float zA = 0.f, zB = 0.f;

    int j = beg;
    for (; j + 1 < end; j += 2) {
        int sA = g_csr[j];
        int sB = g_csr[j + 1];
        float vA = __ldg(&el[sA * NH + head]) + erh;
        float vB = __ldg(&el[sB * NH + head]) + erh;
        vA = vA > 0.f ? vA : 0.2f * vA;
        vB = vB > 0.f ? vB : 0.2f * vB;
        float aA = __expf(vA);
        float aB = __expf(vB);
        float4 hA = ((const float4*)h)[sA * 32 + lane];
        float4 hB = ((const float4*)h)[sB * 32 + lane];
        zA += aA;
        zB += aB;
        accA.x = fmaf(aA, hA.x, accA.x);
        accA.y = fmaf(aA, hA.y, accA.y);
        accA.z = fmaf(aA, hA.z, accA.z);
        accA.w = fmaf(aA, hA.w, accA.w);
        accB.x = fmaf(aB, hB.x, accB.x);
        accB.y = fmaf(aB, hB.y, accB.y);
        accB.z = fmaf(aB, hB.z, accB.z);
        accB.w = fmaf(aB, hB.w, accB.w);
    }
    if (j < end) {
        int s = g_csr[j];
        float v = __ldg(&el[s * NH + head]) + erh;
        v = v > 0.f ? v : 0.2f * v;
        float a = __expf(v);
        float4 hv = ((const float4*)h)[s * 32 + lane];
        zA += a;
        accA.x = fmaf(a, hv.x, accA.x);
        accA.y = fmaf(a, hv.y, accA.y);
        accA.z = fmaf(a, hv.z, accA.z);
        accA.w = fmaf(a, hv.w, accA.w);
    }

    float z = zA + zB;
    float4 acc = make_float4(accA.x + accB.x, accA.y + accB.y,
                             accA.z + accB.z, accA.w + accB.w);
    float invz = (end > beg) ? 1.0f / z : 0.f;   // deg-0 -> output 0 (matches ref)
    acc.x *= invz; acc.y *= invz; acc.z *= invz; acc.w *= invz;

    if (mode) {  // layer 1: activation + split write for gemm2
        acc.x = acc.x > 0.f ? acc.x : 0.01f * acc.x;
        acc.y = acc.y > 0.f ? acc.y : 0.01f * acc.y;
        acc.z = acc.z > 0.f ? acc.z : 0.01f * acc.z;
        acc.w = acc.w > 0.f ? acc.w : 0.01f * acc.w;
        ((uint4*)outs)[w * 32 + lane] = split4(acc);
    } else {
        ((float4*)outf)[w * 32 + lane] = acc;
    }
}

// ---------------- launch ----------------
// Two-stream graph (CSR chain || layer-1 compute).
extern "C" void kernel_launch(void* const* d_in, const int* in_sizes, int n_in,
                              void* d_out, int out_size) {
    const float* x   = (const float*)d_in[0];
    const int*   src = (const int*)d_in[1];
    const int*   dst = (const int*)d_in[2];
    const float* W1  = (const float*)d_in[3];
    const float* al1 = (const float*)d_in[4];
    const float* ar1 = (const float*)d_in[5];
    const float* W2  = (const float*)d_in[6];
    const float* al2 = (const float*)d_in[7];
    const float* ar2 = (const float*)d_in[8];
    float* out = (float*)d_out;
    int E = in_sizes[1];

    float *ph, *pel, *per;
    uint32_t *pwt, *pxs;
    cudaGetSymbolAddress((void**)&ph,  g_h);
    cudaGetSymbolAddress((void**)&pel, g_el);
    cudaGetSymbolAddress((void**)&per, g_er);
    cudaGetSymbolAddress((void**)&pwt, g_wt);
    cudaGetSymbolAddress((void**)&pxs, g_xs);

    // one-time host-side resources (no device memory involved)
    static cudaStream_t s2 = nullptr;
    static cudaEvent_t ev_fork = nullptr, ev_csr = nullptr,
                       ev_gemm1 = nullptr, ev_w2 = nullptr;
    if (s2 == nullptr) {
        cudaStreamCreateWithFlags(&s2, cudaStreamNonBlocking);
        cudaEventCreateWithFlags(&ev_fork,  cudaEventDisableTiming);
        cudaEventCreateWithFlags(&ev_csr,   cudaEventDisableTiming);
        cudaEventCreateWithFlags(&ev_gemm1, cudaEventDisableTiming);
        cudaEventCreateWithFlags(&ev_w2,    cudaEventDisableTiming);
    }

    const int GB = (NN + 63) / 64;        // gemm blocks
    const int XB = (NN * 32 + 255) / 256; // x_split blocks

    cudaEventRecord(ev_fork, 0);
    cudaStreamWaitEvent(s2, ev_fork, 0);

    // main: layer-1 compute chain; s2: CSR build chain
    w_split_kernel<<<32, 256>>>(W1, pwt);                                   // main
    hist_kernel<<<(E + 255) / 256, 256, 0, s2>>>(dst, E);                   // s2
    x_split_kernel<<<XB, 256>>>(x, pxs);                                    // main
    partial_scan_kernel<<<NB, 256, 0, s2>>>();                              // s2
    gemm_mma<<<GB, 256>>>(pxs, pwt, al1, ar1, ph, pel, per);                // main
    scan_bsum_kernel<<<1, 32, 0, s2>>>();                                   // s2
    finalize_kernel<<<(NN + 255) / 256, 256, 0, s2>>>();                    // s2
    scatter_kernel<<<(E + 255) / 256, 256, 0, s2>>>(src, dst, E);           // s2
    cudaEventRecord(ev_csr, s2);
    cudaEventRecord(ev_gemm1, 0);

    // wsplit2 on side stream after gemm1 releases g_wt
    cudaStreamWaitEvent(s2, ev_gemm1, 0);
    w_split_kernel<<<32, 256, 0, s2>>>(W2, pwt);                            // s2
    cudaEventRecord(ev_w2, s2);

    // join: agg1 needs the CSR; writes split directly into g_xs for gemm2
    cudaStreamWaitEvent(0, ev_csr, 0);
    agg_kernel<<<NN / 8, 256>>>(ph, pel, per, nullptr, pxs, 1);             // main

    // layer 2
    cudaStreamWaitEvent(0, ev_w2, 0);
    gemm_mma<<<GB, 256>>>(pxs, pwt, al2, ar2, ph, pel, per);                // main
    agg_kernel<<<NN / 8, 256>>>(ph, pel, per, out, nullptr, 0);             // main
}

// round 16
// speedup vs baseline: 1.0440x; 1.0104x over previous
#include <cuda_runtime.h>
#include <cuda_bf16.h>
#include <stdint.h>

#define NN 50000
#define EE 800000
#define DH 128
#define NH 8
#define SCAN_CHUNK 2048
#define NB ((NN + SCAN_CHUNK - 1) / SCAN_CHUNK)   // 25 scan blocks
#define NA 25024                                   // pipeline split point (64- and 8-divisible)

// ---------------- device scratch (no cudaMalloc allowed) ----------------
__device__ float    g_h[NN * DH];     // per-layer projected features h = x@W
__device__ float    g_o[NN * DH];     // layer-1 output (activated)
__device__ float    g_el[NN * NH];    // attention left logits
__device__ float    g_er[NN * NH];    // attention right logits
__device__ int      g_off[NN + 1];    // CSR row offsets (by dst)
__device__ int      g_cur[NN];        // scatter cursors
__device__ int      g_cnt[NN];        // in-degree histogram
__device__ int      g_csr[EE];        // src node per CSR slot
__device__ int      g_bsum[NB];
__device__ int      g_bbase[NB + 1];
// W split to bf16 hi/lo, fragment-layout chunk-major (see w_split_kernel)
__device__ uint32_t g_wt[128 * 128];  // 64KB

// ---------------- bf16 helpers ----------------
__device__ __forceinline__ uint32_t pack_bf16(float a, float b) {
    __nv_bfloat162 t = __floats2bfloat162_rn(a, b);
    return *(uint32_t*)&t;
}
__device__ __forceinline__ float bf16_hi(float v) {
    return __bfloat162float(__float2bfloat16_rn(v));
}
// D += A(16x16) * B(16x8), bf16 inputs, f32 accum
__device__ __forceinline__ void mma_bf16(float* c, const uint32_t* a,
                                         uint32_t b0, uint32_t b1) {
    asm("mma.sync.aligned.m16n8k16.row.col.f32.bf16.bf16.f32 "
        "{%0,%1,%2,%3}, {%4,%5,%6,%7}, {%8,%9}, {%0,%1,%2,%3};"
        : "+f"(c[0]), "+f"(c[1]), "+f"(c[2]), "+f"(c[3])
        : "r"(a[0]), "r"(a[1]), "r"(a[2]), "r"(a[3]), "r"(b0), "r"(b1));
}

// ---------------- W pre-split: fp32 -> bf16 hi/lo pairs, chunk-major ----------------
__global__ void w_split_kernel(const float* __restrict__ W, uint32_t* __restrict__ wt) {
    int i = blockIdx.x * 256 + threadIdx.x;   // 8192 pairs
    int c = (i >> 3) & 127;
    int kc = i >> 10;
    int p = i & 7;
    int k0 = kc * 16 + 2 * p;
    float v0 = W[k0 * 128 + c];
    float v1 = W[(k0 + 1) * 128 + c];
    float h0 = bf16_hi(v0), h1 = bf16_hi(v1);
    wt[i * 2]     = pack_bf16(h0, h1);
    wt[i * 2 + 1] = pack_bf16(v0 - h0, v1 - h1);
}

// ---------------- CSR build ----------------
__global__ void hist_kernel(const int* __restrict__ dst, int E) {
    int i = blockIdx.x * blockDim.x + threadIdx.x;
    if (i < E) atomicAdd(&g_cnt[dst[i]], 1);
}

__global__ __launch_bounds__(256) void partial_scan_kernel() {
    __shared__ int ws[8];
    int tid = threadIdx.x, lane = tid & 31, warp = tid >> 5;
    int base = blockIdx.x * SCAN_CHUNK + tid * 8;
    int v[8], s = 0;
    #pragma unroll
    for (int t = 0; t < 8; t++) {
        int i = base + t;
        v[t] = (i < NN) ? g_cnt[i] : 0;
        s += v[t];
    }
    int x = s;
    #pragma unroll
    for (int o = 1; o < 32; o <<= 1) {
        int y = __shfl_up_sync(0xffffffffu, x, o);
        if (lane >= o) x += y;
    }
    if (lane == 31) ws[warp] = x;
    __syncthreads();
    if (tid == 0) {
        int a = 0;
        #pragma unroll
        for (int w = 0; w < 8; w++) { int t = ws[w]; ws[w] = a; a += t; }
    }
    __syncthreads();
    int excl = ws[warp] + x - s;
    #pragma unroll
    for (int t = 0; t < 8; t++) {
        int i = base + t;
        if (i < NN) g_cnt[i] = excl;
        excl += v[t];
    }
    if (tid == 255) g_bsum[blockIdx.x] = ws[7] + x;
}

__global__ void scan_bsum_kernel() {
    int tid = threadIdx.x;
    int v = (tid < NB) ? g_bsum[tid] : 0;
    int x = v;
    #pragma unroll
    for (int o = 1; o < 32; o <<= 1) {
        int y = __shfl_up_sync(0xffffffffu, x, o);
        if (tid >= o) x += y;
    }
    if (tid < NB) g_bbase[tid] = x - v;
    if (tid == 31) g_bbase[NB] = x;
}

__global__ void finalize_kernel() {
    int i = blockIdx.x * blockDim.x + threadIdx.x;
    if (i < NN) {
        int off = g_cnt[i] + g_bbase[i / SCAN_CHUNK];
        g_off[i] = off;
        g_cur[i] = off;
        g_cnt[i] = 0;
    }
    if (i == 0) g_off[NN] = g_bbase[NB];
}

__global__ void scatter_kernel(const int* __restrict__ src,
                               const int* __restrict__ dst, int E) {
    int i = blockIdx.x * blockDim.x + threadIdx.x;
    if (i < E) {
        int p = atomicAdd(&g_cur[dst[i]], 1);
        g_csr[p] = src[i];
    }
}

// ---------------- GEMM via bf16 mma (3xBF16) + fused attn projections ----------------
// Exact R12 structure (known-good, 35.5us/782 blocks); row_base added for the
// split-pipeline layer-2 launches.
__global__ __launch_bounds__(256) void gemm_mma(
    const float* __restrict__ x, const uint32_t* __restrict__ wt,
    const float* __restrict__ al, const float* __restrict__ ar,
    float* __restrict__ h, float* __restrict__ el, float* __restrict__ er,
    int row_base) {
    __shared__ uint32_t xs[2 * 64 * 24];    // 12KB
    __shared__ uint32_t ws[2 * 128 * 24];   // 24KB
    int tid = threadIdx.x, lane = tid & 31, warp = tid >> 5;
    int g = lane >> 2, t = lane & 3;
    int row0 = row_base + blockIdx.x * 64;
    int mh = (warp & 1) * 32;        // m-half
    int nq = (warp >> 1) * 32;       // n-quarter (2 heads)
    int xr = tid >> 2, xq = tid & 3; // x-fill coords

    float c[2][4][4];
    #pragma unroll
    for (int mi = 0; mi < 2; mi++)
        #pragma unroll
        for (int j = 0; j < 4; j++)
            #pragma unroll
            for (int q = 0; q < 4; q++) c[mi][j][q] = 0.f;

    // prologue: fill buffer 0 with chunk 0
    {
        float4 v = make_float4(0.f, 0.f, 0.f, 0.f);
        if (row0 + xr < NN) v = ((const float4*)x)[(row0 + xr) * 32 + xq];
        float hx = bf16_hi(v.x), hy = bf16_hi(v.y);
        float hz = bf16_hi(v.z), hw = bf16_hi(v.w);
        uint4 o;
        o.x = pack_bf16(hx, hy);
        o.y = pack_bf16(v.x - hx, v.y - hy);
        o.z = pack_bf16(hz, hw);
        o.w = pack_bf16(v.z - hz, v.w - hw);
        ((uint4*)xs)[xr * 6 + xq] = o;
        #pragma unroll
        for (int e = 0; e < 2; e++) {
            int i = tid + e * 256;
            uint4 wv = ((const uint4*)wt)[i];
            ((uint4*)ws)[(i >> 2) * 6 + (i & 3)] = wv;
        }
    }

    for (int kc = 0; kc < 8; kc++) {
        __syncthreads();
        int cur = kc & 1, nxt = cur ^ 1;
        const uint2* xs2 = (const uint2*)xs + cur * 768;
        const uint2* ws2 = (const uint2*)ws + cur * 1536;

        // prefetch next chunk to registers
        float4 xv_n = make_float4(0.f, 0.f, 0.f, 0.f);
        uint4 wv0_n, wv1_n;
        if (kc < 7) {
            if (row0 + xr < NN)
                xv_n = ((const float4*)x)[(row0 + xr) * 32 + (kc + 1) * 4 + xq];
            wv0_n = ((const uint4*)(wt + (kc + 1) * 2048))[tid];
            wv1_n = ((const uint4*)(wt + (kc + 1) * 2048))[tid + 256];
        }

        // fragment loads + mma on current buffer
        uint32_t ah[2][4], al_[2][4];
        #pragma unroll
        for (int mi = 0; mi < 2; mi++) {
            int mb = (mh + mi * 16 + g) * 12;
            uint2 v0 = xs2[mb + t];
            uint2 v1 = xs2[mb + 96 + t];
            uint2 v2 = xs2[mb + 4 + t];
            uint2 v3 = xs2[mb + 100 + t];
            ah[mi][0] = v0.x; al_[mi][0] = v0.y;
            ah[mi][1] = v1.x; al_[mi][1] = v1.y;
            ah[mi][2] = v2.x; al_[mi][2] = v2.y;
            ah[mi][3] = v3.x; al_[mi][3] = v3.y;
        }
        #pragma unroll
        for (int j = 0; j < 4; j++) {
            int cb = (nq + j * 8 + g) * 12;
            uint2 b0 = ws2[cb + t];
            uint2 b1 = ws2[cb + 4 + t];
            #pragma unroll
            for (int mi = 0; mi < 2; mi++) {
                mma_bf16(c[mi][j], ah[mi],  b0.x, b1.x);   // hi*hi
                mma_bf16(c[mi][j], al_[mi], b0.x, b1.x);   // lo*hi
                mma_bf16(c[mi][j], ah[mi],  b0.y, b1.y);   // hi*lo
            }
        }

        // store prefetched chunk to the other buffer
        if (kc < 7) {
            float hx = bf16_hi(xv_n.x), hy = bf16_hi(xv_n.y);
            float hz = bf16_hi(xv_n.z), hw = bf16_hi(xv_n.w);
            uint4 o;
            o.x = pack_bf16(hx, hy);
            o.y = pack_bf16(xv_n.x - hx, xv_n.y - hy);
            o.z = pack_bf16(hz, hw);
            o.w = pack_bf16(xv_n.z - hz, xv_n.w - hw);
            ((uint4*)xs)[nxt * 384 + xr * 6 + xq] = o;
            ((uint4*)ws)[nxt * 768 + (tid >> 2) * 6 + (tid & 3)] = wv0_n;
            int i = tid + 256;
            ((uint4*)ws)[nxt * 768 + (i >> 2) * 6 + (i & 3)] = wv1_n;
        }
    }

    // epilogue: write h
    #pragma unroll
    for (int mi = 0; mi < 2; mi++)
        #pragma unroll
        for (int j = 0; j < 4; j++) {
            int col = nq + j * 8 + 2 * t;
            int r0 = row0 + mh + mi * 16 + g;
            if (r0 < NN)
                *(float2*)&h[r0 * DH + col] = make_float2(c[mi][j][0], c[mi][j][1]);
            if (r0 + 8 < NN)
                *(float2*)&h[(r0 + 8) * DH + col] = make_float2(c[mi][j][2], c[mi][j][3]);
        }

    // fused attn projections: el/er for this warp's 2 heads, 32 rows
    {
        const float2* alp = (const float2*)al;
        const float2* arp = (const float2*)ar;
        float2 a_l[4], a_r[4];
        #pragma unroll
        for (int j = 0; j < 4; j++) {
            a_l[j] = alp[(nq >> 1) + j * 4 + t];
            a_r[j] = arp[(nq >> 1) + j * 4 + t];
        }
        int head0 = nq >> 4;
        #pragma unroll
        for (int mi = 0; mi < 2; mi++) {
            float e[8];
            e[0] = c[mi][0][0]*a_l[0].x + c[mi][0][1]*a_l[0].y + c[mi][1][0]*a_l[1].x + c[mi][1][1]*a_l[1].y;
            e[1] = c[mi][2][0]*a_l[2].x + c[mi][2][1]*a_l[2].y + c[mi][3][0]*a_l[3].x + c[mi][3][1]*a_l[3].y;
            e[2] = c[mi][0][2]*a_l[0].x + c[mi][0][3]*a_l[0].y + c[mi][1][2]*a_l[1].x + c[mi][1][3]*a_l[1].y;
            e[3] = c[mi][2][2]*a_l[2].x + c[mi][2][3]*a_l[2].y + c[mi][3][2]*a_l[3].x + c[mi][3][3]*a_l[3].y;
            e[4] = c[mi][0][0]*a_r[0].x + c[mi][0][1]*a_r[0].y + c[mi][1][0]*a_r[1].x + c[mi][1][1]*a_r[1].y;
            e[5] = c[mi][2][0]*a_r[2].x + c[mi][2][1]*a_r[2].y + c[mi][3][0]*a_r[3].x + c[mi][3][1]*a_r[3].y;
            e[6] = c[mi][0][2]*a_r[0].x + c[mi][0][3]*a_r[0].y + c[mi][1][2]*a_r[1].x + c[mi][1][3]*a_r[1].y;
            e[7] = c[mi][2][2]*a_r[2].x + c[mi][2][3]*a_r[2].y + c[mi][3][2]*a_r[3].x + c[mi][3][3]*a_r[3].y;
            #pragma unroll
            for (int q = 0; q < 8; q++) {
                e[q] += __shfl_xor_sync(0xffffffffu, e[q], 1);
                e[q] += __shfl_xor_sync(0xffffffffu, e[q], 2);
            }
            if (t == 0) {
                int r0 = row0 + mh + mi * 16 + g;
                if (r0 < NN) {
                    el[r0 * NH + head0]     = e[0];
                    el[r0 * NH + head0 + 1] = e[1];
                    er[r0 * NH + head0]     = e[4];
                    er[r0 * NH + head0 + 1] = e[5];
                }
                if (r0 + 8 < NN) {
                    el[(r0 + 8) * NH + head0]     = e[2];
                    el[(r0 + 8) * NH + head0 + 1] = e[3];
                    er[(r0 + 8) * NH + head0]     = e[6];
                    er[(r0 + 8) * NH + head0 + 1] = e[7];
                }
            }
        }
    }
}

// ---------------- fused edge softmax + aggregation: one warp per dst node ----------------
// Processes node range [wbase, wbase+wcount).
__global__ __launch_bounds__(256) void agg_kernel(
    const float* __restrict__ h, const float* __restrict__ el,
    const float* __restrict__ er, float* __restrict__ out, int act,
    int wbase, int wcount) {
    int w = wbase + blockIdx.x * 8 + (threadIdx.x >> 5);
    if (w >= wbase + wcount || w >= NN) return;
    int lane = threadIdx.x & 31;
    int head = lane >> 2;
    int beg = g_off[w], end = g_off[w + 1];

    float erh = __ldg(&er[w * NH + head]);

    float4 accA = make_float4(0.f, 0.f, 0.f, 0.f);
    float4 accB = make_float4(0.f, 0.f, 0.f, 0.f);
    float zA = 0.f, zB = 0.f;

    int j = beg;
    for (; j + 1 < end; j += 2) {
        int sA = g_csr[j];
        int sB = g_csr[j + 1];
        float vA = __ldg(&el[sA * NH + head]) + erh;
        float vB = __ldg(&el[sB * NH + head]) + erh;
        vA = vA > 0.f ? vA : 0.2f * vA;
        vB = vB > 0.f ? vB : 0.2f * vB;
        float aA = __expf(vA);
        float aB = __expf(vB);
        float4 hA = ((const float4*)h)[sA * 32 + lane];
        float4 hB = ((const float4*)h)[sB * 32 + lane];
        zA += aA;
        zB += aB;
        accA.x = fmaf(aA, hA.x, accA.x);
        accA.y = fmaf(aA, hA.y, accA.y);
        accA.z = fmaf(aA, hA.z, accA.z);
        accA.w = fmaf(aA, hA.w, accA.w);
        accB.x = fmaf(aB, hB.x, accB.x);
        accB.y = fmaf(aB, hB.y, accB.y);
        accB.z = fmaf(aB, hB.z, accB.z);
        accB.w = fmaf(aB, hB.w, accB.w);
    }
    if (j < end) {
        int s = g_csr[j];
        float v = __ldg(&el[s * NH + head]) + erh;
        v = v > 0.f ? v : 0.2f * v;
        float a = __expf(v);
        float4 hv = ((const float4*)h)[s * 32 + lane];
        zA += a;
        accA.x = fmaf(a, hv.x, accA.x);
        accA.y = fmaf(a, hv.y, accA.y);
        accA.z = fmaf(a, hv.z, accA.z);
        accA.w = fmaf(a, hv.w, accA.w);
    }

    float z = zA + zB;
    float4 acc = make_float4(accA.x + accB.x, accA.y + accB.y,
                             accA.z + accB.z, accA.w + accB.w);
    float invz = (end > beg) ? 1.0f / z : 0.f;   // deg-0 -> output 0 (matches ref)
    acc.x *= invz; acc.y *= invz; acc.z *= invz; acc.w *= invz;

    if (act) {
        acc.x = acc.x > 0.f ? acc.x : 0.01f * acc.x;
        acc.y = acc.y > 0.f ? acc.y : 0.01f * acc.y;
        acc.z = acc.z > 0.f ? acc.z : 0.01f * acc.z;
        acc.w = acc.w > 0.f ? acc.w : 0.01f * acc.w;
    }
    ((float4*)out)[w * 32 + lane] = acc;
}

// ---------------- launch ----------------
// Two-stream graph. New in this round: agg1 split into A (rows 0..NA) on main
// and B (rows NA..NN) on s2, so agg1_B overlaps gemm2_A.
extern "C" void kernel_launch(void* const* d_in, const int* in_sizes, int n_in,
                              void* d_out, int out_size) {
    const float* x   = (const float*)d_in[0];
    const int*   src = (const int*)d_in[1];
    const int*   dst = (const int*)d_in[2];
    const float* W1  = (const float*)d_in[3];
    const float* al1 = (const float*)d_in[4];
    const float* ar1 = (const float*)d_in[5];
    const float* W2  = (const float*)d_in[6];
    const float* al2 = (const float*)d_in[7];
    const float* ar2 = (const float*)d_in[8];
    float* out = (float*)d_out;
    int E = in_sizes[1];

    float *ph, *po, *pel, *per;
    uint32_t *pwt;
    cudaGetSymbolAddress((void**)&ph,  g_h);
    cudaGetSymbolAddress((void**)&po,  g_o);
    cudaGetSymbolAddress((void**)&pel, g_el);
    cudaGetSymbolAddress((void**)&per, g_er);
    cudaGetSymbolAddress((void**)&pwt, g_wt);

    // one-time host-side resources (no device memory involved)
    static cudaStream_t s2 = nullptr;
    static cudaEvent_t ev_fork = nullptr, ev_csr = nullptr,
                       ev_g1 = nullptr, ev_w2 = nullptr, ev_a1b = nullptr;
    if (s2 == nullptr) {
        cudaStreamCreateWithFlags(&s2, cudaStreamNonBlocking);
        cudaEventCreateWithFlags(&ev_fork, cudaEventDisableTiming);
        cudaEventCreateWithFlags(&ev_csr,  cudaEventDisableTiming);
        cudaEventCreateWithFlags(&ev_g1,   cudaEventDisableTiming);
        cudaEventCreateWithFlags(&ev_w2,   cudaEventDisableTiming);
        cudaEventCreateWithFlags(&ev_a1b,  cudaEventDisableTiming);
    }

    const int GB  = (NN + 63) / 64;       // full gemm blocks (782)
    const int GA  = NA / 64;              // layer-2 part A blocks (391)
    const int GB2 = (NN - NA + 63) / 64;  // layer-2 part B blocks (391)
    const int AB_A = NA / 8;              // agg part A blocks (3128)
    const int AB_B = (NN - NA + 7) / 8;   // agg part B blocks (3122)

    cudaEventRecord(ev_fork, 0);
    cudaStreamWaitEvent(s2, ev_fork, 0);

    // submission order keeps gemm1 at my launch idx 3 (ncu -s 5 capture)
    w_split_kernel<<<32, 256>>>(W1, pwt);                                    // 0 main
    hist_kernel<<<(E + 255) / 256, 256, 0, s2>>>(dst, E);                    // 1 s2
    partial_scan_kernel<<<NB, 256, 0, s2>>>();                               // 2 s2
    gemm_mma<<<GB, 256>>>(x, pwt, al1, ar1, ph, pel, per, 0);                // 3 main (ncu)
    scan_bsum_kernel<<<1, 32, 0, s2>>>();                                    // 4 s2
    finalize_kernel<<<(NN + 255) / 256, 256, 0, s2>>>();                     // 5 s2
    scatter_kernel<<<(E + 255) / 256, 256, 0, s2>>>(src, dst, E);            // 6 s2
    cudaEventRecord(ev_csr, s2);
    cudaEventRecord(ev_g1, 0);

    // s2: after gemm1 releases g_wt -> wsplit2, then agg1_B (CSR-ordered on s2)
    cudaStreamWaitEvent(s2, ev_g1, 0);
    w_split_kernel<<<32, 256, 0, s2>>>(W2, pwt);                             // s2
    cudaEventRecord(ev_w2, s2);
    agg_kernel<<<AB_B, 256, 0, s2>>>(ph, pel, per, po, 1, NA, NN - NA);      // s2
    cudaEventRecord(ev_a1b, s2);

    // main: agg1_A (needs CSR), then gemm2_A overlapping agg1_B
    cudaStreamWaitEvent(0, ev_csr, 0);
    agg_kernel<<<AB_A, 256>>>(ph, pel, per, po, 1, 0, NA);                   // main
    cudaStreamWaitEvent(0, ev_w2, 0);
    gemm_mma<<<GA, 256>>>(po, pwt, al2, ar2, ph, pel, per, 0);               // main
    cudaStreamWaitEvent(0, ev_a1b, 0);
    gemm_mma<<<GB2, 256>>>(po, pwt, al2, ar2, ph, pel, per, NA);             // main
    agg_kernel<<<NN / 8, 256>>>(ph, pel, per, out, 0, 0, NN);                // main
}

// round 17
// speedup vs baseline: 1.0990x; 1.0527x over previous
#include <cuda_runtime.h>
#include <cuda_bf16.h>
#include <stdint.h>

#define NN 50000
#define EE 800000
#define DH 128
#define NH 8
#define SCAN_CHUNK 2048
#define NB ((NN + SCAN_CHUNK - 1) / SCAN_CHUNK)   // 25 scan blocks

// ---------------- device scratch (no cudaMalloc allowed) ----------------
__device__ float    g_h[NN * DH];     // per-layer projected features h = x@W
__device__ float    g_o[NN * DH];     // layer-1 output (activated)
__device__ float    g_el[NN * NH];    // attention left logits
__device__ float    g_er[NN * NH];    // attention right logits
__device__ int      g_off[NN + 1];    // CSR row offsets (by dst)
__device__ int      g_cur[NN];        // scatter cursors
__device__ int      g_cnt[NN];        // in-degree histogram
__device__ int      g_csr[EE];        // src node per CSR slot
__device__ int      g_bsum[NB];
__device__ int      g_bbase[NB + 1];
// W split to bf16 hi/lo, fragment-layout chunk-major (see w_split_kernel)
__device__ uint32_t g_wt[128 * 128];  // 64KB

// ---------------- bf16 helpers ----------------
__device__ __forceinline__ uint32_t pack_bf16(float a, float b) {
    __nv_bfloat162 t = __floats2bfloat162_rn(a, b);
    return *(uint32_t*)&t;
}
__device__ __forceinline__ float bf16_hi(float v) {
    return __bfloat162float(__float2bfloat16_rn(v));
}
// D += A(16x16) * B(16x8), bf16 inputs, f32 accum
__device__ __forceinline__ void mma_bf16(float* c, const uint32_t* a,
                                         uint32_t b0, uint32_t b1) {
    asm("mma.sync.aligned.m16n8k16.row.col.f32.bf16.bf16.f32 "
        "{%0,%1,%2,%3}, {%4,%5,%6,%7}, {%8,%9}, {%0,%1,%2,%3};"
        : "+f"(c[0]), "+f"(c[1]), "+f"(c[2]), "+f"(c[3])
        : "r"(a[0]), "r"(a[1]), "r"(a[2]), "r"(a[3]), "r"(b0), "r"(b1));
}

// ---------------- W pre-split: fp32 -> bf16 hi/lo pairs, chunk-major ----------------
__global__ void w_split_kernel(const float* __restrict__ W, uint32_t* __restrict__ wt) {
    int i = blockIdx.x * 256 + threadIdx.x;   // 8192 pairs
    int c = (i >> 3) & 127;
    int kc = i >> 10;
    int p = i & 7;
    int k0 = kc * 16 + 2 * p;
    float v0 = W[k0 * 128 + c];
    float v1 = W[(k0 + 1) * 128 + c];
    float h0 = bf16_hi(v0), h1 = bf16_hi(v1);
    wt[i * 2]     = pack_bf16(h0, h1);
    wt[i * 2 + 1] = pack_bf16(v0 - h0, v1 - h1);
}

// ---------------- CSR build ----------------
__global__ void hist_kernel(const int* __restrict__ dst, int E) {
    int i = blockIdx.x * blockDim.x + threadIdx.x;
    if (i < E) atomicAdd(&g_cnt[dst[i]], 1);
}

__global__ __launch_bounds__(256) void partial_scan_kernel() {
    __shared__ int ws[8];
    int tid = threadIdx.x, lane = tid & 31, warp = tid >> 5;
    int base = blockIdx.x * SCAN_CHUNK + tid * 8;
    int v[8], s = 0;
    #pragma unroll
    for (int t = 0; t < 8; t++) {
        int i = base + t;
        v[t] = (i < NN) ? g_cnt[i] : 0;
        s += v[t];
    }
    int x = s;
    #pragma unroll
    for (int o = 1; o < 32; o <<= 1) {
        int y = __shfl_up_sync(0xffffffffu, x, o);
        if (lane >= o) x += y;
    }
    if (lane == 31) ws[warp] = x;
    __syncthreads();
    if (tid == 0) {
        int a = 0;
        #pragma unroll
        for (int w = 0; w < 8; w++) { int t = ws[w]; ws[w] = a; a += t; }
    }
    __syncthreads();
    int excl = ws[warp] + x - s;
    #pragma unroll
    for (int t = 0; t < 8; t++) {
        int i = base + t;
        if (i < NN) g_cnt[i] = excl;
        excl += v[t];
    }
    if (tid == 255) g_bsum[blockIdx.x] = ws[7] + x;
}

__global__ void scan_bsum_kernel() {
    int tid = threadIdx.x;
    int v = (tid < NB) ? g_bsum[tid] : 0;
    int x = v;
    #pragma unroll
    for (int o = 1; o < 32; o <<= 1) {
        int y = __shfl_up_sync(0xffffffffu, x, o);
        if (tid >= o) x += y;
    }
    if (tid < NB) g_bbase[tid] = x - v;
    if (tid == 31) g_bbase[NB] = x;
}

__global__ void finalize_kernel() {
    int i = blockIdx.x * blockDim.x + threadIdx.x;
    if (i < NN) {
        int off = g_cnt[i] + g_bbase[i / SCAN_CHUNK];
        g_off[i] = off;
        g_cur[i] = off;
        g_cnt[i] = 0;
    }
    if (i == 0) g_off[NN] = g_bbase[NB];
}

__global__ void scatter_kernel(const int* __restrict__ src,
                               const int* __restrict__ dst, int E) {
    int i = blockIdx.x * blockDim.x + threadIdx.x;
    if (i < E) {
        int p = atomicAdd(&g_cur[dst[i]], 1);
        g_csr[p] = src[i];
    }
}

// ---------------- GEMM via bf16 mma (3xBF16) + fused attn projections ----------------
// R12 structure with the kc loop FULLY UNROLLED: all smem offsets become
// compile-time constants on loop-invariant bases (kills per-iteration IMAD/LEA),
// and min-3-blocks launch bound raises occupancy 22% -> 33%+.
__global__ __launch_bounds__(256, 3) void gemm_mma(
    const float* __restrict__ x, const uint32_t* __restrict__ wt,
    const float* __restrict__ al, const float* __restrict__ ar,
    float* __restrict__ h, float* __restrict__ el, float* __restrict__ er) {
    __shared__ uint32_t xs[2 * 64 * 24];    // 12KB
    __shared__ uint32_t ws[2 * 128 * 24];   // 24KB
    int tid = threadIdx.x, lane = tid & 31, warp = tid >> 5;
    int g = lane >> 2, t = lane & 3;
    int row0 = blockIdx.x * 64;
    int mh = (warp & 1) * 32;        // m-half
    int nq = (warp >> 1) * 32;       // n-quarter (2 heads)
    int xr = tid >> 2, xq = tid & 3; // x-fill coords
    bool xvalid = (row0 + xr) < NN;

    // loop-invariant fragment bases (u64 index space)
    int mb0 = (mh + g) * 12 + t;          // A m-tile 0
    int mb1 = (mh + 16 + g) * 12 + t;     // A m-tile 1
    int cb0 = (nq + g) * 12 + t;          // B n-tiles j=0..3 at +0,+96,+192,+288
    // x store/fill bases (uint4 index space)
    int xfill = xr * 6 + xq;
    int wfill0 = (tid >> 2) * 6 + (tid & 3);
    int wfill1 = ((tid + 256) >> 2) * 6 + ((tid + 256) & 3);

    float c[2][4][4];
    #pragma unroll
    for (int mi = 0; mi < 2; mi++)
        #pragma unroll
        for (int j = 0; j < 4; j++)
            #pragma unroll
            for (int q = 0; q < 4; q++) c[mi][j][q] = 0.f;

    // prologue: fill buffer 0 with chunk 0
    {
        float4 v = make_float4(0.f, 0.f, 0.f, 0.f);
        if (xvalid) v = ((const float4*)x)[(row0 + xr) * 32 + xq];
        float hx = bf16_hi(v.x), hy = bf16_hi(v.y);
        float hz = bf16_hi(v.z), hw = bf16_hi(v.w);
        uint4 o;
        o.x = pack_bf16(hx, hy);
        o.y = pack_bf16(v.x - hx, v.y - hy);
        o.z = pack_bf16(hz, hw);
        o.w = pack_bf16(v.z - hz, v.w - hw);
        ((uint4*)xs)[xfill] = o;
        #pragma unroll
        for (int e = 0; e < 2; e++) {
            int i = tid + e * 256;
            uint4 wv = ((const uint4*)wt)[i];
            ((uint4*)ws)[(i >> 2) * 6 + (i & 3)] = wv;
        }
    }

    #pragma unroll
    for (int kc = 0; kc < 8; kc++) {
        __syncthreads();
        const int cur = kc & 1, nxt = cur ^ 1;
        const uint2* xs2 = (const uint2*)xs + cur * 768;
        const uint2* ws2 = (const uint2*)ws + cur * 1536;

        // prefetch next chunk to registers
        float4 xv_n = make_float4(0.f, 0.f, 0.f, 0.f);
        uint4 wv0_n, wv1_n;
        if (kc < 7) {
            if (xvalid)
                xv_n = ((const float4*)x)[(row0 + xr) * 32 + (kc + 1) * 4 + xq];
            wv0_n = ((const uint4*)(wt + (kc + 1) * 2048))[tid];
            wv1_n = ((const uint4*)(wt + (kc + 1) * 2048))[tid + 256];
        }

        // fragment loads + mma on current buffer (static offsets after unroll)
        uint32_t ah[2][4], al_[2][4];
        {
            uint2 v0 = xs2[mb0];
            uint2 v1 = xs2[mb0 + 96];
            uint2 v2 = xs2[mb0 + 4];
            uint2 v3 = xs2[mb0 + 100];
            ah[0][0] = v0.x; al_[0][0] = v0.y;
            ah[0][1] = v1.x; al_[0][1] = v1.y;
            ah[0][2] = v2.x; al_[0][2] = v2.y;
            ah[0][3] = v3.x; al_[0][3] = v3.y;
            v0 = xs2[mb1];
            v1 = xs2[mb1 + 96];
            v2 = xs2[mb1 + 4];
            v3 = xs2[mb1 + 100];
            ah[1][0] = v0.x; al_[1][0] = v0.y;
            ah[1][1] = v1.x; al_[1][1] = v1.y;
            ah[1][2] = v2.x; al_[1][2] = v2.y;
            ah[1][3] = v3.x; al_[1][3] = v3.y;
        }
        #pragma unroll
        for (int j = 0; j < 4; j++) {
            uint2 b0 = ws2[cb0 + j * 96];
            uint2 b1 = ws2[cb0 + j * 96 + 4];
            #pragma unroll
            for (int mi = 0; mi < 2; mi++) {
                mma_bf16(c[mi][j], ah[mi],  b0.x, b1.x);   // hi*hi
                mma_bf16(c[mi][j], al_[mi], b0.x, b1.x);   // lo*hi
                mma_bf16(c[mi][j], ah[mi],  b0.y, b1.y);   // hi*lo
            }
        }

        // store prefetched chunk to the other buffer
        if (kc < 7) {
            float hx = bf16_hi(xv_n.x), hy = bf16_hi(xv_n.y);
            float hz = bf16_hi(xv_n.z), hw = bf16_hi(xv_n.w);
            uint4 o;
            o.x = pack_bf16(hx, hy);
            o.y = pack_bf16(xv_n.x - hx, xv_n.y - hy);
            o.z = pack_bf16(hz, hw);
            o.w = pack_bf16(xv_n.z - hz, xv_n.w - hw);
            ((uint4*)xs)[nxt * 384 + xfill] = o;
            ((uint4*)ws)[nxt * 768 + wfill0] = wv0_n;
            ((uint4*)ws)[nxt * 768 + wfill1] = wv1_n;
        }
    }

    // epilogue: write h
    #pragma unroll
    for (int mi = 0; mi < 2; mi++)
        #pragma unroll
        for (int j = 0; j < 4; j++) {
            int col = nq + j * 8 + 2 * t;
            int r0 = row0 + mh + mi * 16 + g;
            if (r0 < NN)
                *(float2*)&h[r0 * DH + col] = make_float2(c[mi][j][0], c[mi][j][1]);
            if (r0 + 8 < NN)
                *(float2*)&h[(r0 + 8) * DH + col] = make_float2(c[mi][j][2], c[mi][j][3]);
        }

    // fused attn projections: el/er for this warp's 2 heads, 32 rows
    {
        const float2* alp = (const float2*)al;
        const float2* arp = (const float2*)ar;
        float2 a_l[4], a_r[4];
        #pragma unroll
        for (int j = 0; j < 4; j++) {
            a_l[j] = alp[(nq >> 1) + j * 4 + t];
            a_r[j] = arp[(nq >> 1) + j * 4 + t];
        }
        int head0 = nq >> 4;
        #pragma unroll
        for (int mi = 0; mi < 2; mi++) {
            float e[8];
            e[0] = c[mi][0][0]*a_l[0].x + c[mi][0][1]*a_l[0].y + c[mi][1][0]*a_l[1].x + c[mi][1][1]*a_l[1].y;
            e[1] = c[mi][2][0]*a_l[2].x + c[mi][2][1]*a_l[2].y + c[mi][3][0]*a_l[3].x + c[mi][3][1]*a_l[3].y;
            e[2] = c[mi][0][2]*a_l[0].x + c[mi][0][3]*a_l[0].y + c[mi][1][2]*a_l[1].x + c[mi][1][3]*a_l[1].y;
            e[3] = c[mi][2][2]*a_l[2].x + c[mi][2][3]*a_l[2].y + c[mi][3][2]*a_l[3].x + c[mi][3][3]*a_l[3].y;
            e[4] = c[mi][0][0]*a_r[0].x + c[mi][0][1]*a_r[0].y + c[mi][1][0]*a_r[1].x + c[mi][1][1]*a_r[1].y;
            e[5] = c[mi][2][0]*a_r[2].x + c[mi][2][1]*a_r[2].y + c[mi][3][0]*a_r[3].x + c[mi][3][1]*a_r[3].y;
            e[6] = c[mi][0][2]*a_r[0].x + c[mi][0][3]*a_r[0].y + c[mi][1][2]*a_r[1].x + c[mi][1][3]*a_r[1].y;
            e[7] = c[mi][2][2]*a_r[2].x + c[mi][2][3]*a_r[2].y + c[mi][3][2]*a_r[3].x + c[mi][3][3]*a_r[3].y;
            #pragma unroll
            for (int q = 0; q < 8; q++) {
                e[q] += __shfl_xor_sync(0xffffffffu, e[q], 1);
                e[q] += __shfl_xor_sync(0xffffffffu, e[q], 2);
            }
            if (t == 0) {
                int r0 = row0 + mh + mi * 16 + g;
                if (r0 < NN) {
                    el[r0 * NH + head0]     = e[0];
                    el[r0 * NH + head0 + 1] = e[1];
                    er[r0 * NH + head0]     = e[4];
                    er[r0 * NH + head0 + 1] = e[5];
                }
                if (r0 + 8 < NN) {
                    el[(r0 + 8) * NH + head0]     = e[2];
                    el[(r0 + 8) * NH + head0 + 1] = e[3];
                    er[(r0 + 8) * NH + head0]     = e[6];
                    er[(r0 + 8) * NH + head0 + 1] = e[7];
                }
            }
        }
    }
}

// ---------------- fused edge softmax + aggregation: one warp per dst node ----------------
__global__ __launch_bounds__(256) void agg_kernel(
    const float* __restrict__ h, const float* __restrict__ el,
    const float* __restrict__ er, float* __restrict__ out, int act) {
    int w = blockIdx.x * 8 + (threadIdx.x >> 5);
    if (w >= NN) return;
    int lane = threadIdx.x & 31;
    int head = lane >> 2;
    int beg = g_off[w], end = g_off[w + 1];

    float erh = __ldg(&er[w * NH + head]);

    float4 accA = make_float4(0.f, 0.f, 0.f, 0.f);
    float4 accB = make_float4(0.f, 0.f, 0.f, 0.f);
    float zA = 0.f, zB = 0.f;

    int j = beg;
    for (; j + 1 < end; j += 2) {
        int sA = g_csr[j];
        int sB = g_csr[j + 1];
        float vA = __ldg(&el[sA * NH + head]) + erh;
        float vB = __ldg(&el[sB * NH + head]) + erh;
        vA = vA > 0.f ? vA : 0.2f * vA;
        vB = vB > 0.f ? vB : 0.2f * vB;
        float aA = __expf(vA);
        float aB = __expf(vB);
        float4 hA = ((const float4*)h)[sA * 32 + lane];
        float4 hB = ((const float4*)h)[sB * 32 + lane];
        zA += aA;
        zB += aB;
        accA.x = fmaf(aA, hA.x, accA.x);
        accA.y = fmaf(aA, hA.y, accA.y);
        accA.z = fmaf(aA, hA.z, accA.z);
        accA.w = fmaf(aA, hA.w, accA.w);
        accB.x = fmaf(aB, hB.x, accB.x);
        accB.y = fmaf(aB, hB.y, accB.y);
        accB.z = fmaf(aB, hB.z, accB.z);
        accB.w = fmaf(aB, hB.w, accB.w);
    }
    if (j < end) {
        int s = g_csr[j];
        float v = __ldg(&el[s * NH + head]) + erh;
        v = v > 0.f ? v : 0.2f * v;
        float a = __expf(v);
        float4 hv = ((const float4*)h)[s * 32 + lane];
        zA += a;
        accA.x = fmaf(a, hv.x, accA.x);
        accA.y = fmaf(a, hv.y, accA.y);
        accA.z = fmaf(a, hv.z, accA.z);
        accA.w = fmaf(a, hv.w, accA.w);
    }

    float z = zA + zB;
    float4 acc = make_float4(accA.x + accB.x, accA.y + accB.y,
                             accA.z + accB.z, accA.w + accB.w);
    float invz = (end > beg) ? 1.0f / z : 0.f;   // deg-0 -> output 0 (matches ref)
    acc.x *= invz; acc.y *= invz; acc.z *= invz; acc.w *= invz;

    if (act) {
        acc.x = acc.x > 0.f ? acc.x : 0.01f * acc.x;
        acc.y = acc.y > 0.f ? acc.y : 0.01f * acc.y;
        acc.z = acc.z > 0.f ? acc.z : 0.01f * acc.z;
        acc.w = acc.w > 0.f ? acc.w : 0.01f * acc.w;
    }
    ((float4*)out)[w * 32 + lane] = acc;
}

// ---------------- launch ----------------
// Two-stream graph (CSR chain || layer-1 compute) — exact R12 topology.
extern "C" void kernel_launch(void* const* d_in, const int* in_sizes, int n_in,
                              void* d_out, int out_size) {
    const float* x   = (const float*)d_in[0];
    const int*   src = (const int*)d_in[1];
    const int*   dst = (const int*)d_in[2];
    const float* W1  = (const float*)d_in[3];
    const float* al1 = (const float*)d_in[4];
    const float* ar1 = (const float*)d_in[5];
    const float* W2  = (const float*)d_in[6];
    const float* al2 = (const float*)d_in[7];
    const float* ar2 = (const float*)d_in[8];
    float* out = (float*)d_out;
    int E = in_sizes[1];

    float *ph, *po, *pel, *per;
    uint32_t *pwt;
    cudaGetSymbolAddress((void**)&ph,  g_h);
    cudaGetSymbolAddress((void**)&po,  g_o);
    cudaGetSymbolAddress((void**)&pel, g_el);
    cudaGetSymbolAddress((void**)&per, g_er);
    cudaGetSymbolAddress((void**)&pwt, g_wt);

    // one-time host-side resources (no device memory involved)
    static cudaStream_t s2 = nullptr;
    static cudaEvent_t ev_fork = nullptr, ev_csr = nullptr,
                       ev_gemm1 = nullptr, ev_w2 = nullptr;
    if (s2 == nullptr) {
        cudaStreamCreateWithFlags(&s2, cudaStreamNonBlocking);
        cudaEventCreateWithFlags(&ev_fork,  cudaEventDisableTiming);
        cudaEventCreateWithFlags(&ev_csr,   cudaEventDisableTiming);
        cudaEventCreateWithFlags(&ev_gemm1, cudaEventDisableTiming);
        cudaEventCreateWithFlags(&ev_w2,    cudaEventDisableTiming);
    }

    const int GB = (NN + 63) / 64;   // gemm blocks

    cudaEventRecord(ev_fork, 0);
    cudaStreamWaitEvent(s2, ev_fork, 0);

    w_split_kernel<<<32, 256>>>(W1, pwt);                                   // 0 main
    hist_kernel<<<(E + 255) / 256, 256, 0, s2>>>(dst, E);                   // 1 s2
    partial_scan_kernel<<<NB, 256, 0, s2>>>();                              // 2 s2
    gemm_mma<<<GB, 256>>>(x, pwt, al1, ar1, ph, pel, per);                  // 3 main (ncu)
    scan_bsum_kernel<<<1, 32, 0, s2>>>();                                   // 4 s2
    finalize_kernel<<<(NN + 255) / 256, 256, 0, s2>>>();                    // 5 s2
    scatter_kernel<<<(E + 255) / 256, 256, 0, s2>>>(src, dst, E);           // 6 s2
    cudaEventRecord(ev_csr, s2);
    cudaEventRecord(ev_gemm1, 0);

    // wsplit2 on side stream after gemm1 releases g_wt
    cudaStreamWaitEvent(s2, ev_gemm1, 0);
    w_split_kernel<<<32, 256, 0, s2>>>(W2, pwt);                            // 7 s2
    cudaEventRecord(ev_w2, s2);

    // join: agg1 needs the CSR
    cudaStreamWaitEvent(0, ev_csr, 0);
    agg_kernel<<<NN / 8, 256>>>(ph, pel, per, po, 1);                       // 8 main

    // layer 2
    cudaStreamWaitEvent(0, ev_w2, 0);
    gemm_mma<<<GB, 256>>>(po, pwt, al2, ar2, ph, pel, per);                 // 9 main
    agg_kernel<<<NN / 8, 256>>>(ph, pel, per, out, 0);                      // 10 main
}